// round 17
// baseline (speedup 1.0000x reference)
#include <cuda_runtime.h>

// GVCNN group pooling collapsed to out[n,c] = sum_v coef[n,gid[n,v]] * RPs[n,v,c].
//
// R11 champion skeleton (64-thread block, channel-split across 2 warps,
// batched 12xLDG.128 register tile, 27-SHFL transpose-reduce, ONE
// __syncthreads, redundant match_any binning, warp-independent epilogue)
// extended with ONE-SAMPLE-LOOKAHEAD register ping-pong: each block handles
// 4 consecutive samples; the 12 batched loads for sample i+1 are issued
// BEFORE computing sample i, so the ~450cyc per-sample compute tail always
// has the next tile in flight (the duty-cycle hole that capped R6-R16 at
// ~70% DRAM). s_y is parity-double-buffered so it stays 1 barrier/sample.
// Unlike R8: 1 barrier (not 3), warp-independent epilogue, 3/4 of computes
// prefetch-covered.  2x48-reg tiles + misc ~= 126 regs -> (64,8).

#define NV  12
#define SPB 4
#define EPSF 1e-6f

__global__ __launch_bounds__(64, 8) void gvcnn_kernel(
    const float4* __restrict__ RPs4,   // [N, 12, 64] float4
    const float4* __restrict__ w4p,    // [64] float4
    const float*  __restrict__ b,
    float4*       __restrict__ out4)   // [N, 64] float4
{
    const int lane = threadIdx.x & 31;
    const int half = threadIdx.x >> 5;           // warp 0: chunks 0..31, warp 1: 32..63
    const int u    = half * 32 + lane;           // owned float4 chunk
    const size_t n0 = (size_t)blockIdx.x * SPB;

    __shared__ float s_y[2][2][NV];              // [iter parity][warp][view]

    const float4 wv = w4p[u];
    const float  bb = b[0];

    // ---- batched tile load: 12 independent coalesced LDG.128 ----
    auto load_tile = [&](float4 (&r)[NV], size_t n) {
        const float4* base = RPs4 + n * (NV * 64) + u;
#pragma unroll
        for (int v = 0; v < NV; v++) r[v] = base[v * 64];
    };

    // ---- full per-sample compute (R11 body), s_y slot by parity ----
    auto process = [&](const float4 (&r)[NV], size_t n, int par) {
        float p[NV];
#pragma unroll
        for (int v = 0; v < NV; v++)
            p[v] = r[v].x * wv.x + r[v].y * wv.y + r[v].z * wv.z + r[v].w * wv.w;

#pragma unroll
        for (int i = 0; i < NV; i++)
            p[i] += __shfl_xor_sync(0xffffffffu, p[i], 16);

        const bool b8 = (lane & 8) != 0;
        const bool b4 = (lane & 4) != 0;
        const bool b2 = (lane & 2) != 0;
        const bool b1 = (lane & 1) != 0;

        float q8[8];
#pragma unroll
        for (int i = 0; i < 8; i++) {
            const float hiv  = (i + 8 < NV) ? p[i + 8] : 0.f;
            const float send = b8 ? p[i] : hiv;
            const float recv = __shfl_xor_sync(0xffffffffu, send, 8);
            q8[i] = (b8 ? hiv : p[i]) + recv;
        }
        float q4[4];
#pragma unroll
        for (int i = 0; i < 4; i++) {
            const float send = b4 ? q8[i] : q8[i + 4];
            const float recv = __shfl_xor_sync(0xffffffffu, send, 4);
            q4[i] = (b4 ? q8[i + 4] : q8[i]) + recv;
        }
        float q2[2];
#pragma unroll
        for (int i = 0; i < 2; i++) {
            const float send = b2 ? q4[i] : q4[i + 2];
            const float recv = __shfl_xor_sync(0xffffffffu, send, 2);
            q2[i] = (b2 ? q4[i + 2] : q4[i]) + recv;
        }
        float yh;
        {
            const float send = b1 ? q2[0] : q2[1];
            const float recv = __shfl_xor_sync(0xffffffffu, send, 1);
            yh = (b1 ? q2[1] : q2[0]) + recv;
        }

        if (lane < NV) s_y[par][half][lane] = yh;
        __syncthreads();                         // the ONLY barrier per sample

        const int vl = (lane < NV) ? lane : 0;
        const float y = s_y[par][0][vl] + s_y[par][1][vl];

        const float x  = fabsf(y + bb) + EPSF;
        const float s  = x / (1.0f + x);                 // == sigmoid(log(x))
        const int  gid = min((int)(s * 10.0f), 9) >> 1;  // 0..4

        const unsigned mask = __match_any_sync(0xffffffffu, gid) & 0xFFFu;
        const int      gszI = __popc(mask);
        const float    gszF = (float)(gszI | (gszI == 0));
        const float    val  = ceilf(s * gszF);

        float numer = 0.f;
#pragma unroll
        for (int uu = 0; uu < NV; uu++) {
            const float vu = __shfl_sync(0xffffffffu, val, uu);
            if ((mask >> uu) & 1u) numer += vu;
        }
        const float gs = numer / (gszF + EPSF);          // group_score

        float t = (lane < NV) ? gs / gszF : 0.f;
#pragma unroll
        for (int off = 16; off > 0; off >>= 1)
            t += __shfl_xor_sync(0xffffffffu, t, off);

        const float coef = gs / (gszF + EPSF) * (1.0f / (t + EPSF));

        float4 acc = make_float4(0.f, 0.f, 0.f, 0.f);
#pragma unroll
        for (int v = 0; v < NV; v++) {
            const float cfv = __shfl_sync(0xffffffffu, coef, v);
            acc.x += cfv * r[v].x;  acc.y += cfv * r[v].y;
            acc.z += cfv * r[v].z;  acc.w += cfv * r[v].w;
        }
        out4[n * 64 + u] = acc;
    };

    // ---- ping-pong pipeline: prefetch i+1 before computing i ----
    float4 rA[NV], rB[NV];
    load_tile(rA, n0);
    load_tile(rB, n0 + 1);          // in flight during process of n0
    process(rA, n0, 0);
    load_tile(rA, n0 + 2);          // in flight during process of n0+1
    process(rB, n0 + 1, 1);
    load_tile(rB, n0 + 3);          // in flight during process of n0+2
    process(rA, n0 + 2, 0);
    process(rB, n0 + 3, 1);
}

extern "C" void kernel_launch(void* const* d_in, const int* in_sizes, int n_in,
                              void* d_out, int out_size)
{
    const float4* RPs4 = (const float4*)d_in[0];   // [8192,12,256] f32
    const float4* w4p  = (const float4*)d_in[1];   // [256] f32
    const float*  b    = (const float*)d_in[2];    // [1] f32
    float4* out4       = (float4*)d_out;           // [8192,256] f32

    const int n = in_sizes[0] / (NV * 256);        // 8192
    gvcnn_kernel<<<n / SPB, 64>>>(RPs4, w4p, b, out4);
}